// round 15
// baseline (speedup 1.0000x reference)
#include <cuda_runtime.h>
#include <cstdint>
#include <cmath>

// HDCProcessor: bit-domain exponential-decay scan, single fused kernel.
// R15: chunk-pair overlap. Each block runs TWO non-adjacent chunks:
//   phase1: warm-A (store-free; cA=0 stores directly, seeding DRAM early)
//   phase2: store-A interleaved with warm-B  (warm issue hides under DRAM)
//   phase3: store-B
// R14's measured split was warm 13us (DRAM idle) + store 37us (write-bound),
// serialized; overlapping warm-B with store-A removes most exposed warm.
//   hdc[t,d] = 0.3*s(t,d) + 0.7*s(t,d)*s(t-1,d-1)*s(t-2,d-2)  (signs, rolls mod D)
//   acc_t = 0.95*acc_{t-1} + hdc_t ;  out[t] = acc_t * (1-g)/(1-g^{t+1})
// c in {+-1.0, +-0.4}: smem LUT[f1 f0 y1 y0] = {c_j, c_j+1}, broadcast LDS.
// Chunks 0,1 exact; others 128-step warmup (rel ~3.5e-4 measured; gate 1e-3).

#define DDIM     4096
#define NB       8
#define NT       2048
#define NPAIR    8                 // block handles chunks (pair, pair+8)
#define CLEN     128
#define WUP      128
#define NTHREADS 256               // 2 dims per thread
#define NDG      8                 // 4096 dims / (256 thr * 2 dims)
#define ROWW     17                // words per staged row: 1 halo + 16 slice
#define RWORDS   (256 * ROWW)      // 4352
#define ROWB     (ROWW * 4)

__device__ uint32_t g_bitsx[NDG * RWORDS];   // per-dg pre-halo'd packed rows
__device__ float    g_inv[NT];               // (1-g)/(1-g^{t+1})

// ---- packed f32x2 helpers ----
__device__ __forceinline__ unsigned long long pk2(uint32_t lo, uint32_t hi) {
    unsigned long long r;
    asm("mov.b64 %0, {%1, %2};" : "=l"(r) : "r"(lo), "r"(hi));
    return r;
}
#define FMA2(d, a, b, c) \
    asm("fma.rn.f32x2 %0, %1, %2, %3;" : "=l"(d) : "l"(a), "l"(b), "l"(c))
#define MUL2(d, a, b) \
    asm("mul.rn.f32x2 %0, %1, %2;" : "=l"(d) : "l"(a), "l"(b))
#define G2    0x3F7333333F733333ull   // {0.95f, 0.95f}
#define INV05 0x3D4CCCCD3D4CCCCDull   // {0.05f, 0.05f}

// ---- pack: sign bits of the bipolar codebook, expanded per d-group ----
__global__ void pack_kernel(const float* __restrict__ cb) {
    const int row  = blockIdx.x;
    const int lane = threadIdx.x & 31;
    const int wq   = (blockIdx.y << 2) + (threadIdx.x >> 5);  // word quarter 0..15
    for (int k = 0; k < 8; k++) {
        int gw = wq * 8 + k;
        float v = cb[row * DDIM + gw * 32 + lane];
        unsigned m = __ballot_sync(0xffffffffu, v < 0.0f);
        if (lane == 0) {
            g_bitsx[(gw >> 4) * RWORDS + row * ROWW + (gw & 15) + 1] = m;
            int gwn = (gw + 1) & 127;               // this word is the halo of
            if ((gwn & 15) == 0)                    // the next d-group (mod wrap)
                g_bitsx[(gwn >> 4) * RWORDS + row * ROWW] = m;
        }
    }
    if (blockIdx.y == 0) {
        int gid = blockIdx.x * 128 + threadIdx.x;
        if (gid < NT)
            g_inv[gid] = (float)(0.05 / (1.0 - pow(0.95, (double)(gid + 1))));
    }
}

// ---- fused scan, chunk-paired ----
__global__ void __launch_bounds__(NTHREADS)
scan_kernel(const int* __restrict__ idx, float* __restrict__ out)
{
    const int dg   = blockIdx.x;
    const int cA   = blockIdx.y;            // 0..7
    const int b    = blockIdx.z;
    const int t0A  = cA * CLEN;
    const int t0B  = t0A + NPAIR * CLEN;    // chunk cA+8, t0B in [1024, 1920]
    const int tid  = threadIdx.x;

    __shared__ uint32_t s_bits[RWORDS + 4];
    __shared__ alignas(8) int s_idxA[260];   // A: row byte offsets (hist at 0,1)
    __shared__ alignas(8) int s_idxB[260];   // B
    __shared__ unsigned long long s_inv2[CLEN];   // packed {inv,inv} (cA < 3)
    __shared__ unsigned long long s_lut[16];      // packed {c_j, c_j+1}

    if (tid < 16) {
        float c0 = ((tid & 4) ? -0.3f : 0.3f) + ((tid & 1) ? -0.7f : 0.7f);
        float c1 = ((tid & 8) ? -0.3f : 0.3f) + ((tid & 2) ? -0.7f : 0.7f);
        s_lut[tid] = pk2(__float_as_uint(c0), __float_as_uint(c1));
    }
    {
        const uint4* src = (const uint4*)(g_bitsx + dg * RWORDS);
        uint4*       dst = (uint4*)s_bits;
        for (int k = tid; k < RWORDS / 4; k += NTHREADS) dst[k] = src[k];
    }
    const int nwarmA = cA ? WUP : 0;
    const int tsA    = t0A - nwarmA;         // first scanned timestep, stream A
    const int tsB    = t0B - WUP;            // stream B (always warmed)
    for (int k = tid; k < 260; k += NTHREADS) {
        int tA = tsA - 2 + k;                 // tails unused; clamp low only
        s_idxA[k] = ((tA >= 0 && tA < NT) ? idx[b * NT + tA] : 0) * ROWB;
        int tB = tsB - 2 + k;
        s_idxB[k] = ((tB >= 0 && tB < NT) ? idx[b * NT + tB] : 0) * ROWB;
    }
    if (cA < 3 && tid < CLEN) {               // t >= 337 -> inv == 0.05f exactly
        float v = g_inv[t0A + tid];
        s_inv2[tid] = pk2(__float_as_uint(v), __float_as_uint(v));
    }
    __syncthreads();

    // bit field: global dim (dg*512 + m) at staged-row bit (32 + m);
    // this thread: dims 2*tid, 2*tid+1 => bits from p = 30 + 2*tid. Both f
    // (cur) and Y (trigram) carry dim j's sign at bit (2+j).
    const int p   = 30 + 2 * tid;
    const int q   = p >> 5;
    const int rsh = p & 31;
    const char* bbase = (const char*)(s_bits + q);
    const char* lutb  = (const char*)s_lut;

    uint32_t h1A = 0, h2A = 0, h1B = 0, h2B = 0;  // pre-shifted histories
    if (tsA >= 2) {                                // cA >= 2
        const uint32_t* w1 = (const uint32_t*)(bbase + s_idxA[1]);
        const uint32_t* w2 = (const uint32_t*)(bbase + s_idxA[0]);
        h1A = __funnelshift_r(w1[0], w1[1], rsh) << 1;
        h2A = __funnelshift_r(w2[0], w2[1], rsh) << 2;
    }
    {
        const uint32_t* w1 = (const uint32_t*)(bbase + s_idxB[1]);
        const uint32_t* w2 = (const uint32_t*)(bbase + s_idxB[0]);
        h1B = __funnelshift_r(w1[0], w1[1], rsh) << 1;
        h2B = __funnelshift_r(w2[0], w2[1], rsh) << 2;
    }

    unsigned long long aA = 0ull, aB = 0ull;     // packed fp32 accumulators
    float* opA = out + ((size_t)b * NT + t0A) * DDIM + dg * 512 + 2 * tid;
    float* opB = out + ((size_t)b * NT + t0B) * DDIM + dg * 512 + 2 * tid;

#define LSTEP(F, H1, H2, ACC)                                                 \
        const uint32_t Y_ = (F) ^ (H1) ^ (H2);                                \
        const uint32_t o01_ = (((F) & 12u) | ((Y_ >> 2) & 3u)) << 3;          \
        FMA2(ACC, ACC, G2, *(const unsigned long long*)(lutb + o01_));

#define EMITV(ACC, OP, IV)                                                    \
        { unsigned long long o01v;                                            \
          MUL2(o01v, (ACC), (IV));                                            \
          asm volatile("st.global.b64 [%0], %1;"                              \
                       :: "l"(OP), "l"(o01v) : "memory");                     \
          OP += DDIM; }

    // paired core on a named stream; SP even
#define CORE2(SIDX, SP, H1, H2, ACC, E0, E1)                                  \
    {                                                                         \
        const int2 ofs = *(const int2*)((SIDX) + (SP));                       \
        const uint32_t* wpX = (const uint32_t*)(bbase + ofs.x);               \
        const uint32_t fX = __funnelshift_r(wpX[0], wpX[1], rsh);             \
        const uint32_t* wpY = (const uint32_t*)(bbase + ofs.y);               \
        const uint32_t fY = __funnelshift_r(wpY[0], wpY[1], rsh);             \
        { LSTEP(fX, H1, H2, ACC) }                                            \
        E0                                                                    \
        { LSTEP(fY, fX << 1, (H1) << 1, ACC) }                                \
        E1                                                                    \
        H2 = fX << 2;                                                         \
        H1 = fY << 1;                                                         \
    }

    // u-only step for t = 0,1 (reference zeroes shifted-history rows)
#define CORE0(SIDX, SP, H1, H2, ACC)                                          \
    {                                                                         \
        const uint32_t* wp = (const uint32_t*)(bbase + (SIDX)[(SP)]);         \
        const uint32_t f = __funnelshift_r(wp[0], wp[1], rsh);                \
        const uint32_t u0 = ((f << 29) & 0x80000000u) | 0x3E99999Au;          \
        const uint32_t u1 = ((f << 28) & 0x80000000u) | 0x3E99999Au;          \
        FMA2(ACC, ACC, G2, pk2(u0, u1));                                      \
        H2 = (H1) << 1;                                                       \
        H1 = f << 1;                                                          \
    }

    if (cA == 0) {
        // phase 1: store A directly (t = 0..127) — seeds DRAM early
        { CORE0(s_idxA, 2, h1A, h2A, aA) EMITV(aA, opA, s_inv2[0]) }
        { CORE0(s_idxA, 3, h1A, h2A, aA) EMITV(aA, opA, s_inv2[1]) }
#pragma unroll 8
        for (int s = 2; s < CLEN; s += 2) {
            const unsigned long long* ivp = &s_inv2[s];
            CORE2(s_idxA, s + 2, h1A, h2A, aA,
                  { EMITV(aA, opA, ivp[0]) }, { EMITV(aA, opA, ivp[1]) })
        }
        // phase 2: warm B alone
#pragma unroll 8
        for (int s = 0; s < WUP; s += 2) {
            CORE2(s_idxB, s + 2, h1B, h2B, aB, {}, {})
        }
    } else {
        // phase 1: warm A (exact for cA == 1, truncated otherwise)
        int w = 0;
        if (cA == 1) {
            CORE0(s_idxA, 2, h1A, h2A, aA)
            CORE0(s_idxA, 3, h1A, h2A, aA)
            w = 2;
        }
#pragma unroll 8
        for (; w < WUP; w += 2) {
            CORE2(s_idxA, w + 2, h1A, h2A, aA, {}, {})
        }
        // phase 2: store A interleaved with warm B
        if (cA < 3) {
#pragma unroll 4
            for (int s = 0; s < CLEN; s += 2) {
                const unsigned long long* ivp = &s_inv2[s];
                CORE2(s_idxA, WUP + s + 2, h1A, h2A, aA,
                      { EMITV(aA, opA, ivp[0]) }, { EMITV(aA, opA, ivp[1]) })
                CORE2(s_idxB, s + 2, h1B, h2B, aB, {}, {})
            }
        } else {       // t0A >= 384: inv == 0.05f exactly in fp32
#pragma unroll 4
            for (int s = 0; s < CLEN; s += 2) {
                CORE2(s_idxA, WUP + s + 2, h1A, h2A, aA,
                      { EMITV(aA, opA, INV05) }, { EMITV(aA, opA, INV05) })
                CORE2(s_idxB, s + 2, h1B, h2B, aB, {}, {})
            }
        }
    }
    // phase 3: store B (t0B >= 1024 -> inv == 0.05f exactly)
#pragma unroll 8
    for (int s = 0; s < CLEN; s += 2) {
        CORE2(s_idxB, WUP + s + 2, h1B, h2B, aB,
              { EMITV(aB, opB, INV05) }, { EMITV(aB, opB, INV05) })
    }
#undef LSTEP
#undef EMITV
#undef CORE2
#undef CORE0
}

extern "C" void kernel_launch(void* const* d_in, const int* in_sizes, int n_in,
                              void* d_out, int out_size)
{
    const float* cb  = (const float*)d_in[0];   // (256, 4096) f32 bipolar
    const int*   idx = (const int*)d_in[1];     // (8, 2048) i32
    float*       out = (float*)d_out;           // (8, 2048, 4096) f32

    dim3 pgrid(256, 4);
    pack_kernel<<<pgrid, 128>>>(cb);

    dim3 grid(NDG, NPAIR, NB);                  // 8 x 8 x 8 = 512 blocks
    scan_kernel<<<grid, NTHREADS>>>(idx, out);
}

// round 16
// speedup vs baseline: 1.0817x; 1.0817x over previous
#include <cuda_runtime.h>
#include <cstdint>
#include <cmath>

// HDCProcessor: bit-domain exponential-decay scan, single fused kernel.
// R16: chunk-chaining. Each block runs ONE 384-step chain: 128-step warmup
//   then 256 stored steps (two consecutive 128-chunks; the first chunk's
//   store phase doubles as the second's warmup) -> total warp-steps -25%
//   vs R14. Dims split finer (NDG=16, 256 dims/block, 128 thr x 2 dims) to
//   keep 1024 balanced blocks. Core identical to R14's proven LUT core.
//   hdc[t,d] = 0.3*s(t,d) + 0.7*s(t,d)*s(t-1,d-1)*s(t-2,d-2)  (signs, rolls mod D)
//   acc_t = 0.95*acc_{t-1} + hdc_t ;  out[t] = acc_t * (1-g)/(1-g^{t+1})
// Superchunk 0 exact; sc>=1 use a 128-step warmup for their first half
// (truncation ~3.5e-4 rel, measured in R11/R14; gate 1e-3) and a 256-step
// warmup for their second half (strictly more accurate).

#define DDIM     4096
#define NB       8
#define NT       2048
#define NSUPER   8                 // superchunks of 256 timesteps
#define SCLEN    256
#define WUP      128
#define NTHREADS 128               // 2 dims per thread -> 256 dims per block
#define NDG      16                // 4096 / 256
#define ROWW     9                 // words per staged row: 1 halo + 8 slice
#define RWORDS   (256 * ROWW)      // 2304
#define ROWB     (ROWW * 4)        // 36
#define SIDXN    (SCLEN + WUP + 2) // 386

__device__ uint32_t g_bitsx[NDG * RWORDS];   // per-dg pre-halo'd packed rows
__device__ float    g_inv[NT];               // (1-g)/(1-g^{t+1})

// ---- packed f32x2 helpers ----
__device__ __forceinline__ unsigned long long pk2(uint32_t lo, uint32_t hi) {
    unsigned long long r;
    asm("mov.b64 %0, {%1, %2};" : "=l"(r) : "r"(lo), "r"(hi));
    return r;
}
#define FMA2(d, a, b, c) \
    asm("fma.rn.f32x2 %0, %1, %2, %3;" : "=l"(d) : "l"(a), "l"(b), "l"(c))
#define MUL2(d, a, b) \
    asm("mul.rn.f32x2 %0, %1, %2;" : "=l"(d) : "l"(a), "l"(b))
#define G2    0x3F7333333F733333ull   // {0.95f, 0.95f}
#define INV05 0x3D4CCCCD3D4CCCCDull   // {0.05f, 0.05f}

// ---- pack: sign bits of the bipolar codebook, 16 slices with halos ----
__global__ void pack_kernel(const float* __restrict__ cb) {
    const int row  = blockIdx.x;
    const int lane = threadIdx.x & 31;
    const int wq   = (blockIdx.y << 2) + (threadIdx.x >> 5);  // word quarter 0..15
    for (int k = 0; k < 8; k++) {
        int gw = wq * 8 + k;
        float v = cb[row * DDIM + gw * 32 + lane];
        unsigned m = __ballot_sync(0xffffffffu, v < 0.0f);
        if (lane == 0) {
            g_bitsx[(gw >> 3) * RWORDS + row * ROWW + (gw & 7) + 1] = m;
            int gwn = (gw + 1) & 127;               // this word is the halo of
            if ((gwn & 7) == 0)                     // the next slice (mod wrap)
                g_bitsx[(gwn >> 3) * RWORDS + row * ROWW] = m;
        }
    }
    if (blockIdx.y == 0) {
        int gid = blockIdx.x * 128 + threadIdx.x;
        if (gid < NT)
            g_inv[gid] = (float)(0.05 / (1.0 - pow(0.95, (double)(gid + 1))));
    }
}

// ---- fused scan: 128-step warmup + 256-step store chain ----
__global__ void __launch_bounds__(NTHREADS)
scan_kernel(const int* __restrict__ idx, float* __restrict__ out)
{
    const int dg  = blockIdx.x;            // 0..15
    const int sc  = blockIdx.y;            // 0..7
    const int b   = blockIdx.z;
    const int t0  = sc * SCLEN;
    const int tid = threadIdx.x;

    __shared__ uint32_t s_bits[RWORDS + 4];
    __shared__ alignas(8) int s_idx[SIDXN + 2];          // row byte offsets
    __shared__ unsigned long long s_inv2[SCLEN];         // packed {inv, inv}
    __shared__ unsigned long long s_lut[16];             // packed {c_j, c_j+1}

    // c LUT: index [f1 f0 y1 y0]; c = 0.3*(f?-1:+1) + 0.7*(y?-1:+1)
    if (tid < 16) {
        float c0 = ((tid & 4) ? -0.3f : 0.3f) + ((tid & 1) ? -0.7f : 0.7f);
        float c1 = ((tid & 8) ? -0.3f : 0.3f) + ((tid & 2) ? -0.7f : 0.7f);
        s_lut[tid] = pk2(__float_as_uint(c0), __float_as_uint(c1));
    }
    // stage packed codebook slice (contiguous uint4 copy, L2-resident source)
    {
        const uint4* src = (const uint4*)(g_bitsx + dg * RWORDS);
        uint4*       dst = (uint4*)s_bits;
        for (int k = tid; k < RWORDS / 4; k += NTHREADS) dst[k] = src[k];
    }
    const int nwarm = sc ? WUP : 0;
    const int ts    = t0 - nwarm;          // first scanned timestep
    for (int k = tid; k < SIDXN; k += NTHREADS) {
        int t = ts - 2 + k;                // tail entries past nsteps are unused
        s_idx[k] = ((t >= 0 && t < NT) ? idx[b * NT + t] : 0) * ROWB;
    }
    if (sc < 2) {                          // sc >= 2: t >= 512 -> inv == 0.05f
        for (int k = tid; k < SCLEN; k += NTHREADS) {
            float v = g_inv[t0 + k];       // == 0.05f already for t >= 337
            s_inv2[k] = pk2(__float_as_uint(v), __float_as_uint(v));
        }
    }
    __syncthreads();

    // bit field: global dim (dg*256 + m) lives at staged-row bit (32 + m);
    // this thread handles dims m = 2*tid, 2*tid+1 => bits from p = 30 + 2*tid.
    // Both f (cur) and Y (trigram) carry dim j's sign at bit (2+j); the LUT
    // index consumes only bits 2..3 of f and Y, so the 288-bit row suffices.
    const int p   = 30 + 2 * tid;
    const int q   = p >> 5;
    const int rsh = p & 31;
    const char* bbase = (const char*)(s_bits + q);
    const char* lutb  = (const char*)s_lut;

    uint32_t h1s = 0, h2s = 0;   // histories pre-shifted: f_{t-1}<<1, f_{t-2}<<2
    if (ts >= 2) {               // sc >= 1: real history
        const uint32_t* w1 = (const uint32_t*)(bbase + s_idx[1]);
        const uint32_t* w2 = (const uint32_t*)(bbase + s_idx[0]);
        h1s = __funnelshift_r(w1[0], w1[1], rsh) << 1;
        h2s = __funnelshift_r(w2[0], w2[1], rsh) << 2;
    }

    unsigned long long a01 = 0ull;               // packed fp32 accumulator
    float* op = out + ((size_t)b * NT + t0) * DDIM + dg * 256 + 2 * tid;

#define LSTEP(F, H1, H2)                                                      \
        const uint32_t Y_ = (F) ^ (H1) ^ (H2);                                \
        const uint32_t o01_ = (((F) & 12u) | ((Y_ >> 2) & 3u)) << 3;          \
        FMA2(a01, a01, G2, *(const unsigned long long*)(lutb + o01_));

#define EMITV(IV)                                                             \
        unsigned long long o01v;                                              \
        MUL2(o01v, a01, (IV));                                                \
        asm volatile("st.global.b64 [%0], %1;"                                \
                     :: "l"(op), "l"(o01v) : "memory");                       \
        op += DDIM;

    // paired core: sp even; E0/E1 run after each step's acc update
#define CORE2(sp, E0, E1)                                                     \
    {                                                                         \
        const int2 ofs = *(const int2*)(s_idx + (sp));                        \
        const uint32_t* wpA = (const uint32_t*)(bbase + ofs.x);               \
        const uint32_t fA = __funnelshift_r(wpA[0], wpA[1], rsh);             \
        const uint32_t* wpB = (const uint32_t*)(bbase + ofs.y);               \
        const uint32_t fB = __funnelshift_r(wpB[0], wpB[1], rsh);             \
        { LSTEP(fA, h1s, h2s) }                                               \
        E0                                                                    \
        { LSTEP(fB, fA << 1, h1s << 1) }                                      \
        E1                                                                    \
        h2s = fA << 2;                                                        \
        h1s = fB << 1;                                                        \
    }

    // u-only single step for t = 0,1 (reference zeroes shifted-history rows)
#define CORE0(sp)                                                             \
    {                                                                         \
        const uint32_t* wp = (const uint32_t*)(bbase + s_idx[(sp)]);          \
        const uint32_t f = __funnelshift_r(wp[0], wp[1], rsh);                \
        const uint32_t u0 = ((f << 29) & 0x80000000u) | 0x3E99999Au;          \
        const uint32_t u1 = ((f << 28) & 0x80000000u) | 0x3E99999Au;          \
        FMA2(a01, a01, G2, pk2(u0, u1));                                      \
        h2s = h1s << 1;                                                       \
        h1s = f << 1;                                                         \
    }

    if (sc == 0) {
        // exact from t = 0; whole 256-step range stored, table normalizer
        { CORE0(2) EMITV(s_inv2[0]) }
        { CORE0(3) EMITV(s_inv2[1]) }
#pragma unroll 8
        for (int s = 2; s < SCLEN; s += 2) {
            const unsigned long long* ivp = &s_inv2[s];
            CORE2(s + 2, { EMITV(ivp[0]) }, { EMITV(ivp[1]) })
        }
    } else {
        // warmup: 128 store-free steps (ts >= 128, history always real)
#pragma unroll 8
        for (int w = 0; w < WUP; w += 2) { CORE2(w + 2, {}, {}) }
        // store: 256 steps
        if (sc == 1) {                   // t in [256,512): table (mixed region)
#pragma unroll 8
            for (int s = 0; s < SCLEN; s += 2) {
                const unsigned long long* ivp = &s_inv2[s];
                CORE2(WUP + s + 2, { EMITV(ivp[0]) }, { EMITV(ivp[1]) })
            }
        } else {       // t >= 512: (1-g)/(1-g^(t+1)) == 0.05f exactly in fp32
#pragma unroll 8
            for (int s = 0; s < SCLEN; s += 2) {
                CORE2(WUP + s + 2, { EMITV(INV05) }, { EMITV(INV05) })
            }
        }
    }
#undef LSTEP
#undef EMITV
#undef CORE2
#undef CORE0
}

extern "C" void kernel_launch(void* const* d_in, const int* in_sizes, int n_in,
                              void* d_out, int out_size)
{
    const float* cb  = (const float*)d_in[0];   // (256, 4096) f32 bipolar
    const int*   idx = (const int*)d_in[1];     // (8, 2048) i32
    float*       out = (float*)d_out;           // (8, 2048, 4096) f32

    dim3 pgrid(256, 4);
    pack_kernel<<<pgrid, 128>>>(cb);

    dim3 grid(NDG, NSUPER, NB);                 // 16 x 8 x 8 = 1024 blocks
    scan_kernel<<<grid, NTHREADS>>>(idx, out);
}

// round 17
// speedup vs baseline: 1.1522x; 1.0651x over previous
#include <cuda_runtime.h>
#include <cstdint>
#include <cmath>

// HDCProcessor: bit-domain exponential-decay scan, single fused kernel.
// R17: R16 chained base (warm + 256-step store, NDG=16, 1024 blocks) with
//   - WUP 128 -> 112 (chain 368 steps; rel_err ~5.6e-4 by measured geometric
//     scaling from R16's 2.458e-4; gate 1e-3)
//   - inv table computed in-kernel (double pow, sc<2 blocks only): g_inv
//     global pass removed, pack kernel slims to bits only.
//   hdc[t,d] = 0.3*s(t,d) + 0.7*s(t,d)*s(t-1,d-1)*s(t-2,d-2)  (signs, rolls mod D)
//   acc_t = 0.95*acc_{t-1} + hdc_t ;  out[t] = acc_t * (1-g)/(1-g^{t+1})
// c in {+-1.0, +-0.4}: smem LUT[f1 f0 y1 y0] = {c_j, c_j+1}, broadcast LDS.

#define DDIM     4096
#define NB       8
#define NT       2048
#define NSUPER   8                 // superchunks of 256 timesteps
#define SCLEN    256
#define WUP      112
#define NTHREADS 128               // 2 dims per thread -> 256 dims per block
#define NDG      16                // 4096 / 256
#define ROWW     9                 // words per staged row: 1 halo + 8 slice
#define RWORDS   (256 * ROWW)      // 2304
#define ROWB     (ROWW * 4)        // 36
#define SIDXN    (SCLEN + WUP + 2) // 370

__device__ uint32_t g_bitsx[NDG * RWORDS];   // per-dg pre-halo'd packed rows

// ---- packed f32x2 helpers ----
__device__ __forceinline__ unsigned long long pk2(uint32_t lo, uint32_t hi) {
    unsigned long long r;
    asm("mov.b64 %0, {%1, %2};" : "=l"(r) : "r"(lo), "r"(hi));
    return r;
}
#define FMA2(d, a, b, c) \
    asm("fma.rn.f32x2 %0, %1, %2, %3;" : "=l"(d) : "l"(a), "l"(b), "l"(c))
#define MUL2(d, a, b) \
    asm("mul.rn.f32x2 %0, %1, %2;" : "=l"(d) : "l"(a), "l"(b))
#define G2    0x3F7333333F733333ull   // {0.95f, 0.95f}
#define INV05 0x3D4CCCCD3D4CCCCDull   // {0.05f, 0.05f}

// ---- pack: sign bits of the bipolar codebook, 16 slices with halos ----
__global__ void pack_kernel(const float* __restrict__ cb) {
    const int row  = blockIdx.x;
    const int lane = threadIdx.x & 31;
    const int wq   = (blockIdx.y << 2) + (threadIdx.x >> 5);  // word quarter 0..15
    for (int k = 0; k < 8; k++) {
        int gw = wq * 8 + k;
        float v = cb[row * DDIM + gw * 32 + lane];
        unsigned m = __ballot_sync(0xffffffffu, v < 0.0f);
        if (lane == 0) {
            g_bitsx[(gw >> 3) * RWORDS + row * ROWW + (gw & 7) + 1] = m;
            int gwn = (gw + 1) & 127;               // this word is the halo of
            if ((gwn & 7) == 0)                     // the next slice (mod wrap)
                g_bitsx[(gwn >> 3) * RWORDS + row * ROWW] = m;
        }
    }
}

// ---- fused scan: 112-step warmup + 256-step store chain ----
__global__ void __launch_bounds__(NTHREADS)
scan_kernel(const int* __restrict__ idx, float* __restrict__ out)
{
    const int dg  = blockIdx.x;            // 0..15
    const int sc  = blockIdx.y;            // 0..7
    const int b   = blockIdx.z;
    const int t0  = sc * SCLEN;
    const int tid = threadIdx.x;

    __shared__ uint32_t s_bits[RWORDS + 4];
    __shared__ alignas(8) int s_idx[SIDXN + 2];          // row byte offsets
    __shared__ unsigned long long s_inv2[SCLEN];         // packed {inv, inv}
    __shared__ unsigned long long s_lut[16];             // packed {c_j, c_j+1}

    // c LUT: index [f1 f0 y1 y0]; c = 0.3*(f?-1:+1) + 0.7*(y?-1:+1)
    if (tid < 16) {
        float c0 = ((tid & 4) ? -0.3f : 0.3f) + ((tid & 1) ? -0.7f : 0.7f);
        float c1 = ((tid & 8) ? -0.3f : 0.3f) + ((tid & 2) ? -0.7f : 0.7f);
        s_lut[tid] = pk2(__float_as_uint(c0), __float_as_uint(c1));
    }
    // stage packed codebook slice (contiguous uint4 copy, L2-resident source)
    {
        const uint4* src = (const uint4*)(g_bitsx + dg * RWORDS);
        uint4*       dst = (uint4*)s_bits;
        for (int k = tid; k < RWORDS / 4; k += NTHREADS) dst[k] = src[k];
    }
    const int nwarm = sc ? WUP : 0;
    const int ts    = t0 - nwarm;          // first scanned timestep
    for (int k = tid; k < SIDXN; k += NTHREADS) {
        int t = ts - 2 + k;                // tail entries past nsteps are unused
        s_idx[k] = ((t >= 0) ? idx[b * NT + t] : 0) * ROWB;
    }
    if (sc < 2) {                          // sc >= 2: t >= 512 -> inv == 0.05f
        for (int k = tid; k < SCLEN; k += NTHREADS) {
            float v = (float)(0.05 / (1.0 - pow(0.95, (double)(t0 + k + 1))));
            s_inv2[k] = pk2(__float_as_uint(v), __float_as_uint(v));
        }
    }
    __syncthreads();

    // bit field: global dim (dg*256 + m) lives at staged-row bit (32 + m);
    // this thread handles dims m = 2*tid, 2*tid+1 => bits from p = 30 + 2*tid.
    // Both f (cur) and Y (trigram) carry dim j's sign at bit (2+j).
    const int p   = 30 + 2 * tid;
    const int q   = p >> 5;
    const int rsh = p & 31;
    const char* bbase = (const char*)(s_bits + q);
    const char* lutb  = (const char*)s_lut;

    uint32_t h1s = 0, h2s = 0;   // histories pre-shifted: f_{t-1}<<1, f_{t-2}<<2
    if (ts >= 2) {               // sc >= 1: real history
        const uint32_t* w1 = (const uint32_t*)(bbase + s_idx[1]);
        const uint32_t* w2 = (const uint32_t*)(bbase + s_idx[0]);
        h1s = __funnelshift_r(w1[0], w1[1], rsh) << 1;
        h2s = __funnelshift_r(w2[0], w2[1], rsh) << 2;
    }

    unsigned long long a01 = 0ull;               // packed fp32 accumulator
    float* op = out + ((size_t)b * NT + t0) * DDIM + dg * 256 + 2 * tid;

#define LSTEP(F, H1, H2)                                                      \
        const uint32_t Y_ = (F) ^ (H1) ^ (H2);                                \
        const uint32_t o01_ = (((F) & 12u) | ((Y_ >> 2) & 3u)) << 3;          \
        FMA2(a01, a01, G2, *(const unsigned long long*)(lutb + o01_));

#define EMITV(IV)                                                             \
        unsigned long long o01v;                                              \
        MUL2(o01v, a01, (IV));                                                \
        asm volatile("st.global.b64 [%0], %1;"                                \
                     :: "l"(op), "l"(o01v) : "memory");                       \
        op += DDIM;

    // paired core: sp even; E0/E1 run after each step's acc update
#define CORE2(sp, E0, E1)                                                     \
    {                                                                         \
        const int2 ofs = *(const int2*)(s_idx + (sp));                        \
        const uint32_t* wpA = (const uint32_t*)(bbase + ofs.x);               \
        const uint32_t fA = __funnelshift_r(wpA[0], wpA[1], rsh);             \
        const uint32_t* wpB = (const uint32_t*)(bbase + ofs.y);               \
        const uint32_t fB = __funnelshift_r(wpB[0], wpB[1], rsh);             \
        { LSTEP(fA, h1s, h2s) }                                               \
        E0                                                                    \
        { LSTEP(fB, fA << 1, h1s << 1) }                                      \
        E1                                                                    \
        h2s = fA << 2;                                                        \
        h1s = fB << 1;                                                        \
    }

    // u-only single step for t = 0,1 (reference zeroes shifted-history rows)
#define CORE0(sp)                                                             \
    {                                                                         \
        const uint32_t* wp = (const uint32_t*)(bbase + s_idx[(sp)]);          \
        const uint32_t f = __funnelshift_r(wp[0], wp[1], rsh);                \
        const uint32_t u0 = ((f << 29) & 0x80000000u) | 0x3E99999Au;          \
        const uint32_t u1 = ((f << 28) & 0x80000000u) | 0x3E99999Au;          \
        FMA2(a01, a01, G2, pk2(u0, u1));                                      \
        h2s = h1s << 1;                                                       \
        h1s = f << 1;                                                         \
    }

    if (sc == 0) {
        // exact from t = 0; whole 256-step range stored, table normalizer
        { CORE0(2) EMITV(s_inv2[0]) }
        { CORE0(3) EMITV(s_inv2[1]) }
#pragma unroll 8
        for (int s = 2; s < SCLEN; s += 2) {
            const unsigned long long* ivp = &s_inv2[s];
            CORE2(s + 2, { EMITV(ivp[0]) }, { EMITV(ivp[1]) })
        }
    } else {
        // warmup: 112 store-free steps (ts >= 144, history always real)
#pragma unroll 8
        for (int w = 0; w < WUP; w += 2) { CORE2(w + 2, {}, {}) }
        // store: 256 steps
        if (sc == 1) {                   // t in [256,512): table (mixed region)
#pragma unroll 8
            for (int s = 0; s < SCLEN; s += 2) {
                const unsigned long long* ivp = &s_inv2[s];
                CORE2(WUP + s + 2, { EMITV(ivp[0]) }, { EMITV(ivp[1]) })
            }
        } else {       // t >= 512: (1-g)/(1-g^(t+1)) == 0.05f exactly in fp32
#pragma unroll 8
            for (int s = 0; s < SCLEN; s += 2) {
                CORE2(WUP + s + 2, { EMITV(INV05) }, { EMITV(INV05) })
            }
        }
    }
#undef LSTEP
#undef EMITV
#undef CORE2
#undef CORE0
}

extern "C" void kernel_launch(void* const* d_in, const int* in_sizes, int n_in,
                              void* d_out, int out_size)
{
    const float* cb  = (const float*)d_in[0];   // (256, 4096) f32 bipolar
    const int*   idx = (const int*)d_in[1];     // (8, 2048) i32
    float*       out = (float*)d_out;           // (8, 2048, 4096) f32

    dim3 pgrid(256, 4);
    pack_kernel<<<pgrid, 128>>>(cb);

    dim3 grid(NDG, NSUPER, NB);                 // 16 x 8 x 8 = 1024 blocks
    scan_kernel<<<grid, NTHREADS>>>(idx, out);
}